// round 13
// baseline (speedup 1.0000x reference)
#include <cuda_runtime.h>
#include <cuda_fp16.h>
#include <cstdint>

#define BB   32
#define KK_  3
#define NN   512
#define FIN  64
#define FOUT 64
#define TT   64
#define KC   (KK_ * NN)          // 1536
#define CC   (FOUT * TT)         // 4096

__device__ __half g_aeff[(size_t)BB * NN * KC];   // [b][n][k*512+m]
__device__ __half g_xt  [(size_t)BB * KC * CC];   // [b][kc][c]

typedef unsigned long long u64;

__device__ __forceinline__ u64 pk2(float x, float y) {
    u64 r; asm("mov.b64 %0, {%1, %2};" : "=l"(r) : "f"(x), "f"(y)); return r;
}
__device__ __forceinline__ void fma2(u64 &c, u64 a, u64 b) {
    asm("fma.rn.f32x2 %0, %1, %2, %0;" : "+l"(c) : "l"(a), "l"(b));
}
__device__ __forceinline__ void unpk2(u64 v, float &x, float &y) {
    asm("mov.b64 {%0, %1}, %2;" : "=f"(x), "=f"(y) : "l"(v));
}
__device__ __forceinline__ uint32_t h2u(__half2 h) {
    return *(uint32_t*)&h;
}
__device__ __forceinline__ uint32_t smem_u32(const void* p) {
    uint32_t a;
    asm("{ .reg .u64 t; cvta.to.shared.u64 t, %1; cvt.u32.u64 %0, t; }" : "=r"(a) : "l"(p));
    return a;
}
__device__ __forceinline__ void cp16(uint32_t dst, const void* src) {
    asm volatile("cp.async.cg.shared.global [%0], [%1], 16;" :: "r"(dst), "l"(src));
}
__device__ __forceinline__ uint32_t lds32(uint32_t a) {
    uint32_t v; asm("ld.shared.b32 %0, [%1];" : "=r"(v) : "r"(a)); return v;
}
__device__ __forceinline__ uint32_t ldu16(uint32_t a) {
    uint32_t v; asm("ld.shared.u16 %0, [%1];" : "=r"(v) : "r"(a)); return v;
}
__device__ __forceinline__ void mma_f16(float* c, const uint32_t* a, const uint32_t* b) {
    asm("mma.sync.aligned.m16n8k16.row.col.f32.f16.f16.f32 "
        "{%0,%1,%2,%3}, {%4,%5,%6,%7}, {%8,%9}, {%0,%1,%2,%3};"
        : "+f"(c[0]), "+f"(c[1]), "+f"(c[2]), "+f"(c[3])
        : "r"(a[0]), "r"(a[1]), "r"(a[2]), "r"(a[3]), "r"(b[0]), "r"(b[1]));
}
#define CP_COMMIT() asm volatile("cp.async.commit_group;" ::: "memory")
#define CP_WAIT2()  asm volatile("cp.async.wait_group 2;" ::: "memory")

// ---------------------------------------------------------------------------
// K1: softmax + A_eff -> fp16 [b][n][k*512+m]
// ---------------------------------------------------------------------------
__global__ __launch_bounds__(128)
void k_aeff(const float* __restrict__ sc, const float* __restrict__ adj,
            const float* __restrict__ mask, const float* __restrict__ cheb)
{
    int n = blockIdx.x, k = blockIdx.y, b = blockIdx.z;
    const float4* s4 = (const float4*)(sc   + (((size_t)(b * KK_ + k)) * NN + n) * NN);
    const float4* a4 = (const float4*)(adj  + (size_t)n * NN);
    const float4* m4 = (const float4*)(mask + ((size_t)(k * NN + n)) * NN);
    const float4* c4 = (const float4*)(cheb + ((size_t)(k * NN + n)) * NN);
    uint2* o2 = (uint2*)(g_aeff + ((size_t)(b * NN + n)) * KC + k * NN);

    int t = threadIdx.x;
    float4 sv = s4[t], av = a4[t], mv = m4[t];
    float v0 = sv.x + av.x * mv.x;
    float v1 = sv.y + av.y * mv.y;
    float v2 = sv.z + av.z * mv.z;
    float v3 = sv.w + av.w * mv.w;

    float mx = fmaxf(fmaxf(v0, v1), fmaxf(v2, v3));
    __shared__ float red[4];
    #pragma unroll
    for (int o = 16; o; o >>= 1) mx = fmaxf(mx, __shfl_xor_sync(0xffffffffu, mx, o));
    if ((t & 31) == 0) red[t >> 5] = mx;
    __syncthreads();
    mx = fmaxf(fmaxf(red[0], red[1]), fmaxf(red[2], red[3]));
    __syncthreads();

    v0 = __expf(v0 - mx); v1 = __expf(v1 - mx);
    v2 = __expf(v2 - mx); v3 = __expf(v3 - mx);
    float s = v0 + v1 + v2 + v3;
    #pragma unroll
    for (int o = 16; o; o >>= 1) s += __shfl_xor_sync(0xffffffffu, s, o);
    if ((t & 31) == 0) red[t >> 5] = s;
    __syncthreads();
    s = red[0] + red[1] + red[2] + red[3];
    float inv = 1.0f / s;

    float4 cv = c4[t];
    __half2 p0 = __floats2half2_rn(cv.x * v0 * inv, cv.y * v1 * inv);
    __half2 p1 = __floats2half2_rn(cv.z * v2 * inv, cv.w * v3 * inv);
    o2[t] = make_uint2(h2u(p0), h2u(p1));
}

// ---------------------------------------------------------------------------
// K2: XT[b,k,m,c] = sum_i x[b,m,i,t] * Theta[k,i,o] -> fp16
// ---------------------------------------------------------------------------
__global__ __launch_bounds__(256)
void k_xtheta(const float* __restrict__ x, const float* __restrict__ Theta)
{
    int m = blockIdx.x, b = blockIdx.y;
    __shared__ float Xs[FIN * TT];
    __shared__ float Ts[FIN * FOUT];

    int tid = threadIdx.x;
    const float4* xb4 = (const float4*)(x + ((size_t)(b * NN + m)) * (FIN * TT));
    float4* Xs4 = (float4*)Xs;
    #pragma unroll
    for (int r = 0; r < 4; r++) Xs4[tid + r * 256] = xb4[tid + r * 256];

    int tx = tid & 15;
    int ty = tid >> 4;

    for (int k = 0; k < KK_; k++) {
        __syncthreads();
        const float4* th4 = (const float4*)(Theta + (size_t)k * FIN * FOUT);
        float4* Ts4 = (float4*)Ts;
        #pragma unroll
        for (int r = 0; r < 4; r++) Ts4[tid + r * 256] = th4[tid + r * 256];
        __syncthreads();

        u64 acc[4][2] = {};
        #pragma unroll 8
        for (int i = 0; i < FIN; i++) {
            float4 th = ((const float4*)(Ts + i * FOUT))[ty];
            float4 xv = ((const float4*)(Xs + i * TT))[tx];
            u64 b01 = pk2(xv.x, xv.y), b23 = pk2(xv.z, xv.w);
            u64 a0 = pk2(th.x, th.x), a1 = pk2(th.y, th.y);
            u64 a2 = pk2(th.z, th.z), a3 = pk2(th.w, th.w);
            fma2(acc[0][0], a0, b01); fma2(acc[0][1], a0, b23);
            fma2(acc[1][0], a1, b01); fma2(acc[1][1], a1, b23);
            fma2(acc[2][0], a2, b01); fma2(acc[2][1], a2, b23);
            fma2(acc[3][0], a3, b01); fma2(acc[3][1], a3, b23);
        }

        __half* orow = g_xt + ((size_t)((b * KK_ + k) * NN + m)) * CC;
        #pragma unroll
        for (int oi = 0; oi < 4; oi++) {
            float e0, e1, e2, e3;
            unpk2(acc[oi][0], e0, e1);
            unpk2(acc[oi][1], e2, e3);
            __half2 p0 = __floats2half2_rn(e0, e1);
            __half2 p1 = __floats2half2_rn(e2, e3);
            *(uint2*)(orow + (size_t)(ty * 4 + oi) * TT + tx * 4) =
                make_uint2(h2u(p0), h2u(p1));
        }
    }
}

// ---------------------------------------------------------------------------
// K3: mma.sync fp16 (m16n8k16, f32 accum) GEMM + ReLU.
// out[b](512x4096) = g_aeff[b](512x1536) @ g_xt[b](1536x4096)
// CTA M=128, N=256, BK=32; 4-stage cp.async; 256 thr = 8 warps (2M x 4N),
// warp tile 64x64. A smem: [128][32] fp16, 64B rows, XOR-64 swizzle
// (chunk ^= (row>>1)&3): conflict-free staging + k-pair lds32.
// B smem: [32][256+8pad] fp16 rows (528 B); fragments via 2x ld.shared.u16.
// ---------------------------------------------------------------------------
#define A_BYTES  8192
#define B_ROW    528
#define B_BYTES  (32 * B_ROW)               // 16896
#define ST_BYTES (A_BYTES + B_BYTES)        // 25088
#define SMEM_GEMM (4 * ST_BYTES + 1024)

__global__ __launch_bounds__(256, 1)
void k_gemm_tc(float* __restrict__ Cg)
{
    extern __shared__ char dsm[];
    uint32_t base = (smem_u32(dsm) + 1023) & ~1023u;

    int tid  = threadIdx.x;
    int lane = tid & 31, wid = tid >> 5;
    int wm = wid & 1, wn = wid >> 1;        // 2 M-groups x 4 N-groups
    int g = lane >> 2, tig = lane & 3;
    uint32_t sgw = (uint32_t)((g >> 1) & 3);   // swizzle term for fragment rows

    int b = blockIdx.z, nt = blockIdx.y, ct = blockIdx.x;
    const __half* Abase = g_aeff + ((size_t)(b * NN) + nt * 128) * KC;
    const __half* Bbase = g_xt   + (size_t)b * KC * CC + ct * 256;

    const int NCHUNK = KC / 32;   // 48

    float acc[4][8][4] = {};

    // A: 512 16B chunks (2/thread), swizzled; B: 1024 chunks (4/thread)
    #define ISSUE(kt, s) do {                                                   \
        uint32_t stA = base + (s) * ST_BYTES, stB = stA + A_BYTES;              \
        int koff = (kt) * 32;                                                   \
        _Pragma("unroll")                                                       \
        for (int r = 0; r < 2; r++) {                                           \
            int idx = tid + r * 256;                                            \
            int row = idx >> 2, c = idx & 3;                                    \
            uint32_t cs = (uint32_t)(c ^ ((row >> 1) & 3));                     \
            cp16(stA + (uint32_t)(row * 64) + cs * 16,                          \
                 Abase + (size_t)row * KC + koff + c * 8);                      \
        }                                                                       \
        _Pragma("unroll")                                                       \
        for (int r = 0; r < 4; r++) {                                           \
            int idx = tid + r * 256;                                            \
            int krow = idx >> 5, p = idx & 31;                                  \
            cp16(stB + (uint32_t)(krow * B_ROW + p * 16),                       \
                 Bbase + (size_t)(koff + krow) * CC + p * 8);                   \
        }                                                                       \
    } while (0)

    ISSUE(0, 0); CP_COMMIT();
    ISSUE(1, 1); CP_COMMIT();
    ISSUE(2, 2); CP_COMMIT();

    uint32_t bcol = (uint32_t)(wn * 64 + g) * 2;    // byte offset of n within B row

    for (int kt = 0; kt < NCHUNK; kt++) {
        CP_WAIT2();
        __syncthreads();
        int s = kt & 3;
        uint32_t stA = base + s * ST_BYTES, stB = stA + A_BYTES;

        #pragma unroll
        for (int ks = 0; ks < 2; ks++) {          // two k16 steps per 32-chunk
            uint32_t cx0 = (((uint32_t)(2 * ks)) ^ sgw) * 16;
            uint32_t cx1 = (((uint32_t)(2 * ks + 1)) ^ sgw) * 16;
            uint32_t a[4][4], bb[8][2];
            #pragma unroll
            for (int i = 0; i < 4; i++) {
                uint32_t r0 = (uint32_t)(wm * 64 + i * 16 + g) * 64 + (uint32_t)tig * 4;
                a[i][0] = lds32(stA + r0 + cx0);
                a[i][1] = lds32(stA + r0 + cx0 + 512);   // row +8
                a[i][2] = lds32(stA + r0 + cx1);
                a[i][3] = lds32(stA + r0 + cx1 + 512);
            }
            uint32_t krow0 = stB + (uint32_t)(ks * 16 + tig * 2) * B_ROW + bcol;
            #pragma unroll
            for (int j = 0; j < 8; j++) {
                uint32_t off = (uint32_t)(j * 8) * 2;
                uint32_t lo0 = ldu16(krow0 + off);
                uint32_t hi0 = ldu16(krow0 + B_ROW + off);
                uint32_t lo1 = ldu16(krow0 + 8 * B_ROW + off);
                uint32_t hi1 = ldu16(krow0 + 9 * B_ROW + off);
                bb[j][0] = lo0 | (hi0 << 16);
                bb[j][1] = lo1 | (hi1 << 16);
            }
            #pragma unroll
            for (int i = 0; i < 4; i++)
                #pragma unroll
                for (int j = 0; j < 8; j++)
                    mma_f16(acc[i][j], a[i], bb[j]);
        }

        if (kt + 3 < NCHUNK) ISSUE(kt + 3, (kt + 3) & 3);
        CP_COMMIT();
    }

    float* C = Cg + ((size_t)(b * NN) + nt * 128) * CC + ct * 256;
    #pragma unroll
    for (int i = 0; i < 4; i++) {
        int row0 = wm * 64 + i * 16 + g;
        #pragma unroll
        for (int j = 0; j < 8; j++) {
            int col = wn * 64 + j * 8 + tig * 2;
            float2 v0 = make_float2(fmaxf(acc[i][j][0], 0.f), fmaxf(acc[i][j][1], 0.f));
            float2 v1 = make_float2(fmaxf(acc[i][j][2], 0.f), fmaxf(acc[i][j][3], 0.f));
            *(float2*)(C + (size_t)row0 * CC + col) = v0;
            *(float2*)(C + (size_t)(row0 + 8) * CC + col) = v1;
        }
    }
    #undef ISSUE
}

extern "C" void kernel_launch(void* const* d_in, const int* in_sizes, int n_in,
                              void* d_out, int out_size)
{
    const float* x     = (const float*)d_in[0];
    const float* sc    = (const float*)d_in[1];
    const float* adj   = (const float*)d_in[2];
    const float* cheb  = (const float*)d_in[3];
    const float* Theta = (const float*)d_in[4];
    const float* mask  = (const float*)d_in[5];
    float* out = (float*)d_out;
    (void)in_sizes; (void)n_in; (void)out_size;

    cudaFuncSetAttribute(k_gemm_tc, cudaFuncAttributeMaxDynamicSharedMemorySize, SMEM_GEMM);

    k_aeff<<<dim3(NN, KK_, BB), 128>>>(sc, adj, mask, cheb);
    k_xtheta<<<dim3(NN, BB), 256>>>(x, Theta);
    k_gemm_tc<<<dim3(CC / 256, NN / 128, BB), 256, SMEM_GEMM>>>(out);
}

// round 15
// speedup vs baseline: 1.4791x; 1.4791x over previous
#include <cuda_runtime.h>
#include <cstdint>

#define BB   32
#define KK_  3
#define NN   512
#define FIN  64
#define FOUT 64
#define TT   64
#define KC   (KK_ * NN)          // 1536
#define CC   (FOUT * TT)         // 4096

__device__ float g_aeff[(size_t)BB * NN * KC];   // [b][n][k*512+m]  (tf32-rounded)
__device__ float g_xt  [(size_t)BB * KC * CC];   // [b][kc][c]       (tf32-rounded)

typedef unsigned long long u64;

__device__ __forceinline__ float tf32r(float x) {
    float r; asm("cvt.rna.tf32.f32 %0, %1;" : "=f"(r) : "f"(x)); return r;
}
__device__ __forceinline__ uint32_t smem_u32(const void* p) {
    uint32_t a;
    asm("{ .reg .u64 t; cvta.to.shared.u64 t, %1; cvt.u32.u64 %0, t; }" : "=r"(a) : "l"(p));
    return a;
}
__device__ __forceinline__ void cp16(uint32_t dst, const void* src) {
    asm volatile("cp.async.cg.shared.global [%0], [%1], 16;" :: "r"(dst), "l"(src));
}
__device__ __forceinline__ uint32_t lds32(uint32_t a) {
    uint32_t v; asm("ld.shared.b32 %0, [%1];" : "=r"(v) : "r"(a)); return v;
}
__device__ __forceinline__ void mma_tf32(float* c, const uint32_t* a, const uint32_t* b) {
    asm("mma.sync.aligned.m16n8k8.row.col.f32.tf32.tf32.f32 "
        "{%0,%1,%2,%3}, {%4,%5,%6,%7}, {%8,%9}, {%0,%1,%2,%3};"
        : "+f"(c[0]), "+f"(c[1]), "+f"(c[2]), "+f"(c[3])
        : "r"(a[0]), "r"(a[1]), "r"(a[2]), "r"(a[3]), "r"(b[0]), "r"(b[1]));
}
#define CP_COMMIT() asm volatile("cp.async.commit_group;" ::: "memory")
#define CP_WAIT2()  asm volatile("cp.async.wait_group 2;" ::: "memory")
#define SWZ(bo) ((bo) ^ (((bo) >> 3) & 0x70))

// ---------------------------------------------------------------------------
// K1: softmax + A_eff, written [b][n][k*512+m], tf32-rounded  (R11 version)
// ---------------------------------------------------------------------------
__global__ __launch_bounds__(128)
void k_aeff(const float* __restrict__ sc, const float* __restrict__ adj,
            const float* __restrict__ mask, const float* __restrict__ cheb)
{
    int n = blockIdx.x, k = blockIdx.y, b = blockIdx.z;
    const float4* s4 = (const float4*)(sc   + (((size_t)(b * KK_ + k)) * NN + n) * NN);
    const float4* a4 = (const float4*)(adj  + (size_t)n * NN);
    const float4* m4 = (const float4*)(mask + ((size_t)(k * NN + n)) * NN);
    const float4* c4 = (const float4*)(cheb + ((size_t)(k * NN + n)) * NN);
    float4*       o4 = (float4*)(g_aeff + ((size_t)(b * NN + n)) * KC + k * NN);

    int t = threadIdx.x;
    float4 sv = s4[t], av = a4[t], mv = m4[t];
    float v0 = sv.x + av.x * mv.x;
    float v1 = sv.y + av.y * mv.y;
    float v2 = sv.z + av.z * mv.z;
    float v3 = sv.w + av.w * mv.w;

    float mx = fmaxf(fmaxf(v0, v1), fmaxf(v2, v3));
    __shared__ float red[4];
    #pragma unroll
    for (int o = 16; o; o >>= 1) mx = fmaxf(mx, __shfl_xor_sync(0xffffffffu, mx, o));
    if ((t & 31) == 0) red[t >> 5] = mx;
    __syncthreads();
    mx = fmaxf(fmaxf(red[0], red[1]), fmaxf(red[2], red[3]));
    __syncthreads();

    v0 = __expf(v0 - mx); v1 = __expf(v1 - mx);
    v2 = __expf(v2 - mx); v3 = __expf(v3 - mx);
    float s = v0 + v1 + v2 + v3;
    #pragma unroll
    for (int o = 16; o; o >>= 1) s += __shfl_xor_sync(0xffffffffu, s, o);
    if ((t & 31) == 0) red[t >> 5] = s;
    __syncthreads();
    s = red[0] + red[1] + red[2] + red[3];
    float inv = 1.0f / s;

    float4 cv = c4[t];
    float4 ov;
    ov.x = tf32r(cv.x * v0 * inv); ov.y = tf32r(cv.y * v1 * inv);
    ov.z = tf32r(cv.z * v2 * inv); ov.w = tf32r(cv.w * v3 * inv);
    o4[t] = ov;
}

// ---------------------------------------------------------------------------
// K2 (NEW, tensor-core): for each (b,m):  XT_k[o,t] = Theta_k^T @ x[b,m]
// 128 thr = 4 warps (2x2), warp tile 32x32, tf32 m16n8k8.
// Smem stride 72 words (72%32=8 -> fragment bank = 8*tig+g, conflict-free).
// A fragment A[o][i] read as Ts[i*72+o] (transpose-by-indexing).
// ---------------------------------------------------------------------------
#define XS 72
__global__ __launch_bounds__(128)
void k_xtheta_tc(const float* __restrict__ x, const float* __restrict__ Theta)
{
    __shared__ float Xs[FIN * XS];   // x[i][t] padded
    __shared__ float Ts[FIN * XS];   // Theta_k[i][o] padded

    int m = blockIdx.x, b = blockIdx.y;
    int tid = threadIdx.x;
    int lane = tid & 31, wid = tid >> 5;
    int wo = (wid & 1) * 32;         // o-offset of warp tile
    int wt = (wid >> 1) * 32;        // t-offset of warp tile
    int g = lane >> 2, tig = lane & 3;

    // stage x[b,m] (64x64 f32), tf32-rounded
    const float4* xb4 = (const float4*)(x + ((size_t)(b * NN + m)) * (FIN * TT));
    #pragma unroll
    for (int r = 0; r < 8; r++) {
        int idx = tid + r * 128;            // 0..1023 float4
        int row = idx >> 4, p = idx & 15;
        float4 v = xb4[idx];
        v.x = tf32r(v.x); v.y = tf32r(v.y); v.z = tf32r(v.z); v.w = tf32r(v.w);
        *(float4*)&Xs[row * XS + p * 4] = v;
    }

    for (int k = 0; k < KK_; k++) {
        __syncthreads();   // Xs ready (k=0) / prior compute done (k>0)
        const float4* th4 = (const float4*)(Theta + (size_t)k * FIN * FOUT);
        #pragma unroll
        for (int r = 0; r < 8; r++) {
            int idx = tid + r * 128;
            int row = idx >> 4, p = idx & 15;
            float4 v = th4[idx];
            v.x = tf32r(v.x); v.y = tf32r(v.y); v.z = tf32r(v.z); v.w = tf32r(v.w);
            *(float4*)&Ts[row * XS + p * 4] = v;
        }
        __syncthreads();

        float acc[2][4][4] = {};
        #pragma unroll
        for (int ks = 0; ks < 8; ks++) {
            int k0 = ks * 8 + tig;
            uint32_t a[2][4], bb[4][2];
            #pragma unroll
            for (int i = 0; i < 2; i++) {
                int o0 = wo + i * 16 + g;
                a[i][0] = __float_as_uint(Ts[k0 * XS + o0]);
                a[i][1] = __float_as_uint(Ts[k0 * XS + o0 + 8]);
                a[i][2] = __float_as_uint(Ts[(k0 + 4) * XS + o0]);
                a[i][3] = __float_as_uint(Ts[(k0 + 4) * XS + o0 + 8]);
            }
            #pragma unroll
            for (int j = 0; j < 4; j++) {
                int t0 = wt + j * 8 + g;
                bb[j][0] = __float_as_uint(Xs[k0 * XS + t0]);
                bb[j][1] = __float_as_uint(Xs[(k0 + 4) * XS + t0]);
            }
            #pragma unroll
            for (int i = 0; i < 2; i++)
                #pragma unroll
                for (int j = 0; j < 4; j++)
                    mma_tf32(acc[i][j], a[i], bb[j]);
        }

        float* orow = g_xt + ((size_t)((b * KK_ + k) * NN + m)) * CC;
        #pragma unroll
        for (int i = 0; i < 2; i++) {
            int o0 = wo + i * 16 + g;
            #pragma unroll
            for (int j = 0; j < 4; j++) {
                int t0 = wt + j * 8 + tig * 2;
                float2 v0 = make_float2(tf32r(acc[i][j][0]), tf32r(acc[i][j][1]));
                float2 v1 = make_float2(tf32r(acc[i][j][2]), tf32r(acc[i][j][3]));
                *(float2*)(orow + (size_t)o0 * TT + t0) = v0;
                *(float2*)(orow + (size_t)(o0 + 8) * TT + t0) = v1;
            }
        }
    }
}

// ---------------------------------------------------------------------------
// K3: mma.sync tf32 GEMM + ReLU  (R11 version, unchanged)
// CTA tile M=128, N=256, BK=32; 4-stage cp.async; 256 thr = 8 warps (2Mx4N).
// ---------------------------------------------------------------------------
#define A_BYTES  16384
#define B_ROW    1056
#define B_BYTES  (32 * B_ROW)
#define ST_BYTES (A_BYTES + B_BYTES)        // 50176
#define SMEM_GEMM (4 * ST_BYTES + 1024)

__global__ __launch_bounds__(256, 1)
void k_gemm_tc(float* __restrict__ Cg)
{
    extern __shared__ char dsm[];
    uint32_t base = (smem_u32(dsm) + 1023) & ~1023u;

    int tid  = threadIdx.x;
    int lane = tid & 31, wid = tid >> 5;
    int wm = wid & 1, wn = wid >> 1;
    int g = lane >> 2, tig = lane & 3;
    uint32_t xorv = (uint32_t)g << 4;

    int b = blockIdx.z, nt = blockIdx.y, ct = blockIdx.x;
    const float* Abase = g_aeff + ((size_t)(b * NN) + nt * 128) * KC;
    const float* Bbase = g_xt   + (size_t)b * KC * CC + ct * 256;

    const int NCHUNK = KC / 32;   // 48

    float acc[4][8][4] = {};

    #define ISSUE(kt, s) do {                                                   \
        uint32_t stA = base + (s) * ST_BYTES, stB = stA + A_BYTES;              \
        int koff = (kt) * 32;                                                   \
        _Pragma("unroll")                                                       \
        for (int r = 0; r < 4; r++) {                                           \
            int idx = tid + r * 256;                                            \
            int row = idx >> 3, p = idx & 7;                                    \
            cp16(stA + SWZ((uint32_t)(row * 128 + p * 16)),                     \
                 Abase + (size_t)row * KC + koff + p * 4);                      \
        }                                                                       \
        _Pragma("unroll")                                                       \
        for (int r = 0; r < 8; r++) {                                           \
            int idx = tid + r * 256;                                            \
            int krow = idx >> 6, p = idx & 63;                                  \
            cp16(stB + (uint32_t)(krow * B_ROW + p * 16),                       \
                 Bbase + (size_t)(koff + krow) * CC + p * 4);                   \
        }                                                                       \
    } while (0)

    ISSUE(0, 0); CP_COMMIT();
    ISSUE(1, 1); CP_COMMIT();
    ISSUE(2, 2); CP_COMMIT();

    uint32_t bcol = (uint32_t)(wn * 64 + g) * 4;

    for (int kt = 0; kt < NCHUNK; kt++) {
        CP_WAIT2();
        __syncthreads();
        int s = kt & 3;
        uint32_t stA = base + s * ST_BYTES, stB = stA + A_BYTES;

        #pragma unroll
        for (int ks = 0; ks < 4; ks++) {
            uint32_t col0 = ((uint32_t)(ks * 8 + tig) * 4) ^ xorv;
            uint32_t col1 = ((uint32_t)(ks * 8 + tig + 4) * 4) ^ xorv;
            uint32_t brow0 = stB + (uint32_t)(ks * 8 + tig) * B_ROW + bcol;
            uint32_t a[4][4], bb[8][2];
            #pragma unroll
            for (int i = 0; i < 4; i++) {
                uint32_t r0 = (uint32_t)(wm * 64 + i * 16 + g) * 128;
                a[i][0] = lds32(stA + r0 + col0);
                a[i][1] = lds32(stA + r0 + 1024 + col0);
                a[i][2] = lds32(stA + r0 + col1);
                a[i][3] = lds32(stA + r0 + 1024 + col1);
            }
            #pragma unroll
            for (int j = 0; j < 8; j++) {
                bb[j][0] = lds32(brow0 + (uint32_t)(j * 8) * 4);
                bb[j][1] = lds32(brow0 + 4 * B_ROW + (uint32_t)(j * 8) * 4);
            }
            #pragma unroll
            for (int i = 0; i < 4; i++)
                #pragma unroll
                for (int j = 0; j < 8; j++)
                    mma_tf32(acc[i][j], a[i], bb[j]);
        }

        if (kt + 3 < NCHUNK) ISSUE(kt + 3, (kt + 3) & 3);
        CP_COMMIT();
    }

    float* C = Cg + ((size_t)(b * NN) + nt * 128) * CC + ct * 256;
    #pragma unroll
    for (int i = 0; i < 4; i++) {
        int row0 = wm * 64 + i * 16 + g;
        #pragma unroll
        for (int j = 0; j < 8; j++) {
            int col = wn * 64 + j * 8 + tig * 2;
            float2 v0 = make_float2(fmaxf(acc[i][j][0], 0.f), fmaxf(acc[i][j][1], 0.f));
            float2 v1 = make_float2(fmaxf(acc[i][j][2], 0.f), fmaxf(acc[i][j][3], 0.f));
            *(float2*)(C + (size_t)row0 * CC + col) = v0;
            *(float2*)(C + (size_t)(row0 + 8) * CC + col) = v1;
        }
    }
    #undef ISSUE
}

extern "C" void kernel_launch(void* const* d_in, const int* in_sizes, int n_in,
                              void* d_out, int out_size)
{
    const float* x     = (const float*)d_in[0];
    const float* sc    = (const float*)d_in[1];
    const float* adj   = (const float*)d_in[2];
    const float* cheb  = (const float*)d_in[3];
    const float* Theta = (const float*)d_in[4];
    const float* mask  = (const float*)d_in[5];
    float* out = (float*)d_out;
    (void)in_sizes; (void)n_in; (void)out_size;

    cudaFuncSetAttribute(k_gemm_tc, cudaFuncAttributeMaxDynamicSharedMemorySize, SMEM_GEMM);

    k_aeff<<<dim3(NN, KK_, BB), 128>>>(sc, adj, mask, cheb);
    k_xtheta_tc<<<dim3(NN, BB), 128>>>(x, Theta);
    k_gemm_tc<<<dim3(CC / 256, NN / 128, BB), 256, SMEM_GEMM>>>(out);
}

// round 16
// speedup vs baseline: 2.3107x; 1.5622x over previous
#include <cuda_runtime.h>
#include <cuda_fp16.h>
#include <cstdint>

#define BB   32
#define KK_  3
#define NN   512
#define FIN  64
#define FOUT 64
#define TT   64
#define KC   (KK_ * NN)          // 1536
#define CC   (FOUT * TT)         // 4096

// Scratch: fp16 A row-major; fp16 B pair-interleaved [b][kc/2][c][2]
__device__ __half g_aeff[(size_t)BB * NN * KC];      // [b][n][kc]
__device__ __half g_xtP [(size_t)BB * KC * CC];      // [b][kc>>1][c][kc&1]

__device__ __forceinline__ float tf32r(float x) {
    float r; asm("cvt.rna.tf32.f32 %0, %1;" : "=f"(r) : "f"(x)); return r;
}
__device__ __forceinline__ uint32_t h2u(__half2 h) { return *(uint32_t*)&h; }
__device__ __forceinline__ uint32_t smem_u32(const void* p) {
    uint32_t a;
    asm("{ .reg .u64 t; cvta.to.shared.u64 t, %1; cvt.u32.u64 %0, t; }" : "=r"(a) : "l"(p));
    return a;
}
__device__ __forceinline__ void cp16(uint32_t dst, const void* src) {
    asm volatile("cp.async.cg.shared.global [%0], [%1], 16;" :: "r"(dst), "l"(src));
}
__device__ __forceinline__ uint32_t lds32(uint32_t a) {
    uint32_t v; asm("ld.shared.b32 %0, [%1];" : "=r"(v) : "r"(a)); return v;
}
__device__ __forceinline__ void mma_tf32(float* c, const uint32_t* a, const uint32_t* b) {
    asm("mma.sync.aligned.m16n8k8.row.col.f32.tf32.tf32.f32 "
        "{%0,%1,%2,%3}, {%4,%5,%6,%7}, {%8,%9}, {%0,%1,%2,%3};"
        : "+f"(c[0]), "+f"(c[1]), "+f"(c[2]), "+f"(c[3])
        : "r"(a[0]), "r"(a[1]), "r"(a[2]), "r"(a[3]), "r"(b[0]), "r"(b[1]));
}
__device__ __forceinline__ void mma_f16(float* c, const uint32_t* a, const uint32_t* b) {
    asm("mma.sync.aligned.m16n8k16.row.col.f32.f16.f16.f32 "
        "{%0,%1,%2,%3}, {%4,%5,%6,%7}, {%8,%9}, {%0,%1,%2,%3};"
        : "+f"(c[0]), "+f"(c[1]), "+f"(c[2]), "+f"(c[3])
        : "r"(a[0]), "r"(a[1]), "r"(a[2]), "r"(a[3]), "r"(b[0]), "r"(b[1]));
}
#define CP_COMMIT() asm volatile("cp.async.commit_group;" ::: "memory")
#define CP_WAIT2()  asm volatile("cp.async.wait_group 2;" ::: "memory")

// ---------------------------------------------------------------------------
// K1: softmax + A_eff -> fp16 row-major [b][n][k*512+m]
// ---------------------------------------------------------------------------
__global__ __launch_bounds__(128)
void k_aeff(const float* __restrict__ sc, const float* __restrict__ adj,
            const float* __restrict__ mask, const float* __restrict__ cheb)
{
    int n = blockIdx.x, k = blockIdx.y, b = blockIdx.z;
    const float4* s4 = (const float4*)(sc   + (((size_t)(b * KK_ + k)) * NN + n) * NN);
    const float4* a4 = (const float4*)(adj  + (size_t)n * NN);
    const float4* m4 = (const float4*)(mask + ((size_t)(k * NN + n)) * NN);
    const float4* c4 = (const float4*)(cheb + ((size_t)(k * NN + n)) * NN);
    uint2* o2 = (uint2*)(g_aeff + ((size_t)(b * NN + n)) * KC + k * NN);

    int t = threadIdx.x;
    float4 sv = s4[t], av = a4[t], mv = m4[t];
    float v0 = sv.x + av.x * mv.x;
    float v1 = sv.y + av.y * mv.y;
    float v2 = sv.z + av.z * mv.z;
    float v3 = sv.w + av.w * mv.w;

    float mx = fmaxf(fmaxf(v0, v1), fmaxf(v2, v3));
    __shared__ float red[4];
    #pragma unroll
    for (int o = 16; o; o >>= 1) mx = fmaxf(mx, __shfl_xor_sync(0xffffffffu, mx, o));
    if ((t & 31) == 0) red[t >> 5] = mx;
    __syncthreads();
    mx = fmaxf(fmaxf(red[0], red[1]), fmaxf(red[2], red[3]));
    __syncthreads();

    v0 = __expf(v0 - mx); v1 = __expf(v1 - mx);
    v2 = __expf(v2 - mx); v3 = __expf(v3 - mx);
    float s = v0 + v1 + v2 + v3;
    #pragma unroll
    for (int o = 16; o; o >>= 1) s += __shfl_xor_sync(0xffffffffu, s, o);
    if ((t & 31) == 0) red[t >> 5] = s;
    __syncthreads();
    s = red[0] + red[1] + red[2] + red[3];
    float inv = 1.0f / s;

    float4 cv = c4[t];
    __half2 p0 = __floats2half2_rn(cv.x * v0 * inv, cv.y * v1 * inv);
    __half2 p1 = __floats2half2_rn(cv.z * v2 * inv, cv.w * v3 * inv);
    o2[t] = make_uint2(h2u(p0), h2u(p1));
}

// ---------------------------------------------------------------------------
// K2: tf32 tensor-core, TWO m per CTA. XT_k[o,t] = Theta_k^T @ x[b,m]
// Writes g_xtP pair-interleaved: row (k*256+mp), col c: {XT[m0],XT[m1]} half2.
// 128 thr = 4 warps (2x2), warp tile 32x32 per m. Smem stride 72 (conflict-free).
// ---------------------------------------------------------------------------
#define XS 72
#define K2_SMEM (3 * FIN * XS * 4)   // Xs0, Xs1, Ts = 55296 B

__global__ __launch_bounds__(128)
void k_xtheta_tc(const float* __restrict__ x, const float* __restrict__ Theta)
{
    extern __shared__ float sm2[];
    float* Xs0 = sm2;
    float* Xs1 = sm2 + FIN * XS;
    float* Ts  = sm2 + 2 * FIN * XS;

    int mp = blockIdx.x, b = blockIdx.y;
    int m0 = mp * 2;
    int tid = threadIdx.x;
    int lane = tid & 31, wid = tid >> 5;
    int wo = (wid & 1) * 32;
    int wt = (wid >> 1) * 32;
    int g = lane >> 2, tig = lane & 3;

    const float4* xb40 = (const float4*)(x + ((size_t)(b * NN + m0)) * (FIN * TT));
    const float4* xb41 = (const float4*)(x + ((size_t)(b * NN + m0 + 1)) * (FIN * TT));
    #pragma unroll
    for (int r = 0; r < 8; r++) {
        int idx = tid + r * 128;
        int row = idx >> 4, p = idx & 15;
        float4 v = xb40[idx];
        v.x = tf32r(v.x); v.y = tf32r(v.y); v.z = tf32r(v.z); v.w = tf32r(v.w);
        *(float4*)&Xs0[row * XS + p * 4] = v;
        float4 w = xb41[idx];
        w.x = tf32r(w.x); w.y = tf32r(w.y); w.z = tf32r(w.z); w.w = tf32r(w.w);
        *(float4*)&Xs1[row * XS + p * 4] = w;
    }

    for (int k = 0; k < KK_; k++) {
        __syncthreads();
        const float4* th4 = (const float4*)(Theta + (size_t)k * FIN * FOUT);
        #pragma unroll
        for (int r = 0; r < 8; r++) {
            int idx = tid + r * 128;
            int row = idx >> 4, p = idx & 15;
            float4 v = th4[idx];
            v.x = tf32r(v.x); v.y = tf32r(v.y); v.z = tf32r(v.z); v.w = tf32r(v.w);
            *(float4*)&Ts[row * XS + p * 4] = v;
        }
        __syncthreads();

        float ac0[2][4][4] = {}, ac1[2][4][4] = {};
        #pragma unroll
        for (int ks = 0; ks < 8; ks++) {
            int k0 = ks * 8 + tig;
            uint32_t a[2][4], b0[4][2], b1[4][2];
            #pragma unroll
            for (int i = 0; i < 2; i++) {
                int o0 = wo + i * 16 + g;
                a[i][0] = __float_as_uint(Ts[k0 * XS + o0]);
                a[i][1] = __float_as_uint(Ts[k0 * XS + o0 + 8]);
                a[i][2] = __float_as_uint(Ts[(k0 + 4) * XS + o0]);
                a[i][3] = __float_as_uint(Ts[(k0 + 4) * XS + o0 + 8]);
            }
            #pragma unroll
            for (int j = 0; j < 4; j++) {
                int t0 = wt + j * 8 + g;
                b0[j][0] = __float_as_uint(Xs0[k0 * XS + t0]);
                b0[j][1] = __float_as_uint(Xs0[(k0 + 4) * XS + t0]);
                b1[j][0] = __float_as_uint(Xs1[k0 * XS + t0]);
                b1[j][1] = __float_as_uint(Xs1[(k0 + 4) * XS + t0]);
            }
            #pragma unroll
            for (int i = 0; i < 2; i++)
                #pragma unroll
                for (int j = 0; j < 4; j++) {
                    mma_tf32(ac0[i][j], a[i], b0[j]);
                    mma_tf32(ac1[i][j], a[i], b1[j]);
                }
        }

        // pair-row base (halves): [b][k*256+mp][c][2]
        __half* prb = g_xtP + (size_t)b * KC * CC + ((size_t)(k * 256 + mp)) * (CC * 2);
        #pragma unroll
        for (int i = 0; i < 2; i++) {
            int o0 = wo + i * 16 + g;
            #pragma unroll
            for (int j = 0; j < 4; j++) {
                int t0 = wt + j * 8 + tig * 2;
                uint2 v0 = make_uint2(h2u(__floats2half2_rn(ac0[i][j][0], ac1[i][j][0])),
                                      h2u(__floats2half2_rn(ac0[i][j][1], ac1[i][j][1])));
                uint2 v1 = make_uint2(h2u(__floats2half2_rn(ac0[i][j][2], ac1[i][j][2])),
                                      h2u(__floats2half2_rn(ac0[i][j][3], ac1[i][j][3])));
                *(uint2*)(prb + (size_t)(o0 * TT + t0) * 2) = v0;
                *(uint2*)(prb + (size_t)((o0 + 8) * TT + t0) * 2) = v1;
            }
        }
    }
}

// ---------------------------------------------------------------------------
// K3: fp16 m16n8k16 GEMM + ReLU (f32 accum).
// CTA M=128, N=256, BK=32; 4-stage cp.async; 256 thr = 8 warps (2M x 4N),
// warp tile 64x64. A smem: [128][32] f16, 80B-padded rows (banks 20g+tig,
// conflict-free). B smem: 16 pair-rows x [256 c][2] f16, 1056B rows
// (banks 8tig+g, conflict-free). Frag loads: A 4x lds32, B 2x lds32.
// ---------------------------------------------------------------------------
#define AROW 80
#define A_BYTES (128 * AROW)               // 10240
#define BROW 1056
#define B_BYTES (16 * BROW)                // 16896
#define ST_BYTES (A_BYTES + B_BYTES)       // 27136
#define SMEM_GEMM (4 * ST_BYTES + 1024)

__global__ __launch_bounds__(256, 1)
void k_gemm_tc(float* __restrict__ Cg)
{
    extern __shared__ char dsm[];
    uint32_t base = (smem_u32(dsm) + 1023) & ~1023u;

    int tid  = threadIdx.x;
    int lane = tid & 31, wid = tid >> 5;
    int wm = wid & 1, wn = wid >> 1;
    int g = lane >> 2, tig = lane & 3;

    int b = blockIdx.z, nt = blockIdx.y, ct = blockIdx.x;
    const __half* Abase = g_aeff + ((size_t)(b * NN) + nt * 128) * KC;
    const __half* BbaseP = g_xtP + (size_t)b * KC * CC + (size_t)(ct * 256) * 2;

    const int NCHUNK = KC / 32;   // 48

    float acc[4][8][4] = {};

    // A: 512 cp16 (2/thread); B: 1024 cp16 (4/thread)
    #define ISSUE(kt, s) do {                                                   \
        uint32_t stA = base + (s) * ST_BYTES, stB = stA + A_BYTES;              \
        int koff = (kt) * 32;                                                   \
        _Pragma("unroll")                                                       \
        for (int r = 0; r < 2; r++) {                                           \
            int idx = tid + r * 256;                                            \
            int row = idx >> 2, c = idx & 3;                                    \
            cp16(stA + (uint32_t)(row * AROW + c * 16),                         \
                 Abase + (size_t)row * KC + koff + c * 8);                      \
        }                                                                       \
        _Pragma("unroll")                                                       \
        for (int r = 0; r < 4; r++) {                                           \
            int idx = tid + r * 256;                                            \
            int pr = idx >> 6, p = idx & 63;                                    \
            cp16(stB + (uint32_t)(pr * BROW + p * 16),                          \
                 BbaseP + (size_t)((kt) * 16 + pr) * (CC * 2) + p * 8);         \
        }                                                                       \
    } while (0)

    ISSUE(0, 0); CP_COMMIT();
    ISSUE(1, 1); CP_COMMIT();
    ISSUE(2, 2); CP_COMMIT();

    uint32_t bcol = (uint32_t)(wn * 64 + g) * 4;   // byte offset of half2 pair at n

    for (int kt = 0; kt < NCHUNK; kt++) {
        CP_WAIT2();
        __syncthreads();
        int s = kt & 3;
        uint32_t stA = base + s * ST_BYTES, stB = stA + A_BYTES;

        #pragma unroll
        for (int ks = 0; ks < 2; ks++) {          // two k16 steps per 32-chunk
            uint32_t a[4][4], bb[8][2];
            #pragma unroll
            for (int i = 0; i < 4; i++) {
                uint32_t ar = stA + (uint32_t)(wm * 64 + i * 16 + g) * AROW
                                  + (uint32_t)(ks * 32 + tig * 4);
                a[i][0] = lds32(ar);
                a[i][1] = lds32(ar + 8 * AROW);
                a[i][2] = lds32(ar + 16);
                a[i][3] = lds32(ar + 8 * AROW + 16);
            }
            uint32_t br = stB + (uint32_t)(ks * 8 + tig) * BROW + bcol;
            #pragma unroll
            for (int j = 0; j < 8; j++) {
                bb[j][0] = lds32(br + (uint32_t)(j * 32));
                bb[j][1] = lds32(br + 4 * BROW + (uint32_t)(j * 32));
            }
            #pragma unroll
            for (int i = 0; i < 4; i++)
                #pragma unroll
                for (int j = 0; j < 8; j++)
                    mma_f16(acc[i][j], a[i], bb[j]);
        }

        if (kt + 3 < NCHUNK) ISSUE(kt + 3, (kt + 3) & 3);
        CP_COMMIT();
    }

    float* C = Cg + ((size_t)(b * NN) + nt * 128) * CC + ct * 256;
    #pragma unroll
    for (int i = 0; i < 4; i++) {
        int row0 = wm * 64 + i * 16 + g;
        #pragma unroll
        for (int j = 0; j < 8; j++) {
            int col = wn * 64 + j * 8 + tig * 2;
            float2 v0 = make_float2(fmaxf(acc[i][j][0], 0.f), fmaxf(acc[i][j][1], 0.f));
            float2 v1 = make_float2(fmaxf(acc[i][j][2], 0.f), fmaxf(acc[i][j][3], 0.f));
            *(float2*)(C + (size_t)row0 * CC + col) = v0;
            *(float2*)(C + (size_t)(row0 + 8) * CC + col) = v1;
        }
    }
    #undef ISSUE
}

extern "C" void kernel_launch(void* const* d_in, const int* in_sizes, int n_in,
                              void* d_out, int out_size)
{
    const float* x     = (const float*)d_in[0];
    const float* sc    = (const float*)d_in[1];
    const float* adj   = (const float*)d_in[2];
    const float* cheb  = (const float*)d_in[3];
    const float* Theta = (const float*)d_in[4];
    const float* mask  = (const float*)d_in[5];
    float* out = (float*)d_out;
    (void)in_sizes; (void)n_in; (void)out_size;

    cudaFuncSetAttribute(k_xtheta_tc, cudaFuncAttributeMaxDynamicSharedMemorySize, K2_SMEM);
    cudaFuncSetAttribute(k_gemm_tc, cudaFuncAttributeMaxDynamicSharedMemorySize, SMEM_GEMM);

    k_aeff<<<dim3(NN, KK_, BB), 128>>>(sc, adj, mask, cheb);
    k_xtheta_tc<<<dim3(NN / 2, BB), 128, K2_SMEM>>>(x, Theta);
    k_gemm_tc<<<dim3(CC / 256, NN / 128, BB), 256, SMEM_GEMM>>>(out);
}